// round 13
// baseline (speedup 1.0000x reference)
#include <cuda_runtime.h>
#include <cuda_fp16.h>
#include <math.h>
#include <stdint.h>

#define BB 8
#define NN 2048
#define FIN 512
#define FOUT 256
#define ALPHA 0.2f

// Scratch (allocation-free rule: __device__ globals)
__device__ __half   g_WT[FOUT * FIN];       // [n][k] fp16 (wh B operand)
__device__ __half   g_WhT[BB * FOUT * NN];  // [b][n][j] fp16 (attn B operand)
__device__ float    g_f1[BB * NN];
__device__ float    g_f2[BB * NN];
__device__ float2   g_e1[BB * NN];          // {exp(f1), exp(ALPHA*f1)}
__device__ float2   g_e2[BB * NN];          // {exp(f2), exp(ALPHA*f2)}
__device__ unsigned g_m2bits[BB * 2];       // per-batch max e2p/e2n bits (idempotent)

// ---------------------------------------------------------------------------
// mma.sync + cp.async helpers (sm_80 baseline — PTX target-safe)
// ---------------------------------------------------------------------------
__device__ __forceinline__ void mma_f16(float d[4], const uint32_t a[4],
                                        uint32_t b0, uint32_t b1) {
    asm volatile(
        "mma.sync.aligned.m16n8k16.row.col.f32.f16.f16.f32 "
        "{%0,%1,%2,%3}, {%4,%5,%6,%7}, {%8,%9}, {%0,%1,%2,%3};"
        : "+f"(d[0]), "+f"(d[1]), "+f"(d[2]), "+f"(d[3])
        : "r"(a[0]), "r"(a[1]), "r"(a[2]), "r"(a[3]), "r"(b0), "r"(b1));
}
__device__ __forceinline__ void cp_async16(uint32_t dst_smem, const void* src) {
    asm volatile("cp.async.cg.shared.global [%0], [%1], 16;"
                 :: "r"(dst_smem), "l"(src));
}
#define CP_COMMIT() asm volatile("cp.async.commit_group;" ::: "memory")
#define CP_WAIT(n)  asm volatile("cp.async.wait_group %0;" :: "n"(n) : "memory")
__device__ __forceinline__ uint32_t h2bits(float x, float y) {
    __half2 h = __floats2half2_rn(x, y);
    return *(uint32_t*)&h;
}

// ---------------------------------------------------------------------------
// Kernel 0: W [k][n] fp32 -> g_WT [n][k] fp16 (tiled transpose, tiny)
// ---------------------------------------------------------------------------
__global__ __launch_bounds__(256) void wt_kernel(const float* __restrict__ W) {
    __shared__ float tile[32][33];
    const int k0 = blockIdx.x * 32;
    const int n0 = blockIdx.y * 32;
    const int tx = threadIdx.x & 31, ty = threadIdx.x >> 5;
#pragma unroll
    for (int i = 0; i < 32; i += 8)
        tile[ty + i][tx] = W[(size_t)(k0 + ty + i) * FOUT + n0 + tx];
    __syncthreads();
#pragma unroll
    for (int i = 0; i < 32; i += 8)
        g_WT[(size_t)(n0 + ty + i) * FIN + k0 + tx] = __float2half_rn(tile[tx][ty + i]);
}

// ---------------------------------------------------------------------------
// Kernel 1: Wh = h @ W, fp16 m16n8k16 (fp32 acc), fused f1/f2/exp epilogue.
// (unchanged — at its wall)
// ---------------------------------------------------------------------------
#define WH_AS  0
#define WH_BS  1280
#define WH_SA  6400
#define WH_F1P 6912
#define WH_F2P 7168
#define WH_SMEM_F 7424

__global__ __launch_bounds__(256, 2) void wh_tc(const float* __restrict__ h,
                                                const float* __restrict__ aa) {
    extern __shared__ float sm[];
    float* A_s  = sm + WH_AS;
    float* B_s  = sm + WH_BS;
    float* sA   = sm + WH_SA;
    float* f1p  = sm + WH_F1P;
    float* f2p  = sm + WH_F2P;

    const int tid  = threadIdx.x;
    const int warp = tid >> 5;
    const int lane = tid & 31;
    const int mw   = warp >> 2;
    const int nw   = warp & 3;
    const int g    = lane >> 2;
    const int t    = lane & 3;
    const int row0 = blockIdx.x * 64;

    sA[tid]       = aa[tid];
    sA[tid + 256] = aa[tid + 256];

    float acc[2][8][4];
#pragma unroll
    for (int fm = 0; fm < 2; fm++)
#pragma unroll
        for (int fn = 0; fn < 8; fn++)
#pragma unroll
            for (int c = 0; c < 4; c++) acc[fm][fn][c] = 0.f;

    const int r  = tid >> 2, q = tid & 3;
    const int bn = tid >> 2;
    const int bc = tid & 3;
    const uint32_t smem_base = (uint32_t)__cvta_generic_to_shared(sm);

    for (int k0 = 0; k0 < FIN; k0 += 32) {
        {
            const float* src = h + (size_t)(row0 + r) * FIN + k0 + q * 8;
            float4 v0 = *(const float4*)src;
            float4 v1 = *(const float4*)(src + 4);
            float* ad = A_s + r * 20 + q * 4;
            ad[0] = __uint_as_float(h2bits(v0.x, v0.y));
            ad[1] = __uint_as_float(h2bits(v0.z, v0.w));
            ad[2] = __uint_as_float(h2bits(v1.x, v1.y));
            ad[3] = __uint_as_float(h2bits(v1.z, v1.w));
        }
#pragma unroll
        for (int p = 0; p < 4; p++) {
            int n = bn + 64 * p;
            const __half* src = g_WT + (size_t)n * FIN + k0 + bc * 8;
            uint32_t dst = smem_base + (WH_BS + n * 20 + bc * 4) * 4;
            cp_async16(dst, src);
        }
        CP_COMMIT();
        CP_WAIT(0);
        __syncthreads();

#pragma unroll
        for (int fk = 0; fk < 2; fk++) {
            uint32_t A[2][4];
#pragma unroll
            for (int fm = 0; fm < 2; fm++) {
                const float* wa = A_s + (mw * 32 + fm * 16 + g) * 20 + fk * 8 + t;
                A[fm][0] = __float_as_uint(wa[0]);
                A[fm][1] = __float_as_uint(wa[160]);
                A[fm][2] = __float_as_uint(wa[4]);
                A[fm][3] = __float_as_uint(wa[164]);
            }
#pragma unroll
            for (int fn = 0; fn < 8; fn++) {
                const float* wb = B_s + (nw * 64 + fn * 8 + g) * 20 + fk * 8 + t;
                uint32_t b0 = __float_as_uint(wb[0]);
                uint32_t b1 = __float_as_uint(wb[4]);
                mma_f16(acc[0][fn], A[0], b0, b1);
                mma_f16(acc[1][fn], A[1], b0, b1);
            }
        }
        __syncthreads();
    }

#pragma unroll
    for (int fm = 0; fm < 2; fm++) {
        int rr = row0 + mw * 32 + fm * 16 + g;
        int bb = rr >> 11;
        int jj = rr & (NN - 1);
#pragma unroll
        for (int fn = 0; fn < 8; fn++) {
            int col = nw * 64 + fn * 8 + t * 2;
            size_t base = ((size_t)bb * FOUT + col) * NN + jj;
            g_WhT[base]          = __float2half_rn(acc[fm][fn][0]);
            g_WhT[base + NN]     = __float2half_rn(acc[fm][fn][1]);
            g_WhT[base + 8]      = __float2half_rn(acc[fm][fn][2]);
            g_WhT[base + NN + 8] = __float2half_rn(acc[fm][fn][3]);
        }
    }

    {
        float p1[4] = {0.f, 0.f, 0.f, 0.f};
        float p2[4] = {0.f, 0.f, 0.f, 0.f};
#pragma unroll
        for (int fm = 0; fm < 2; fm++)
#pragma unroll
            for (int fn = 0; fn < 8; fn++) {
                int col = nw * 64 + fn * 8 + t * 2;
                float a10 = sA[col], a11 = sA[col + 1];
                float a20 = sA[256 + col], a21 = sA[256 + col + 1];
                p1[fm * 2 + 0] += acc[fm][fn][0] * a10 + acc[fm][fn][1] * a11;
                p1[fm * 2 + 1] += acc[fm][fn][2] * a10 + acc[fm][fn][3] * a11;
                p2[fm * 2 + 0] += acc[fm][fn][0] * a20 + acc[fm][fn][1] * a21;
                p2[fm * 2 + 1] += acc[fm][fn][2] * a20 + acc[fm][fn][3] * a21;
            }
#pragma unroll
        for (int off = 1; off <= 2; off <<= 1)
#pragma unroll
            for (int i = 0; i < 4; i++) {
                p1[i] += __shfl_xor_sync(0xFFFFFFFFu, p1[i], off);
                p2[i] += __shfl_xor_sync(0xFFFFFFFFu, p2[i], off);
            }
        if (t == 0) {
#pragma unroll
            for (int fm = 0; fm < 2; fm++)
#pragma unroll
                for (int hi = 0; hi < 2; hi++) {
                    int rowl = mw * 32 + fm * 16 + g + hi * 8;
                    f1p[rowl * 4 + nw] = p1[fm * 2 + hi];
                    f2p[rowl * 4 + nw] = p2[fm * 2 + hi];
                }
        }
    }
    __syncthreads();
    if (tid < 64) {
        float s1 = ((f1p[tid * 4] + f1p[tid * 4 + 1]) + f1p[tid * 4 + 2]) + f1p[tid * 4 + 3];
        float s2 = ((f2p[tid * 4] + f2p[tid * 4 + 1]) + f2p[tid * 4 + 2]) + f2p[tid * 4 + 3];
        int rr = row0 + tid;
        int bb = rr >> 11;
        g_f1[rr] = s1;
        g_f2[rr] = s2;
        float e2p = __expf(s2), e2n = __expf(ALPHA * s2);
        g_e1[rr] = make_float2(__expf(s1), __expf(ALPHA * s1));
        g_e2[rr] = make_float2(e2p, e2n);
        atomicMax(&g_m2bits[bb * 2 + 0], __float_as_uint(e2p));
        atomicMax(&g_m2bits[bb * 2 + 1], __float_as_uint(e2n));
    }
}

// ---------------------------------------------------------------------------
// Kernel 2: fused masked-softmax aggregation — WARP-SPECIALIZED:
//   warps 0-11 (3/SMSP): rows 0-95 via fp16 mma (tensor pipe)
//   warps 12-15 (1/SMSP): rows 96-127 via FFMA outer product (fma pipe)
// Both read the same fp16 smem tiles (slot s <-> j pair (2s, 2s+1)).
// Balance: 96 mma x 42 = 4032 cyc/SMSP  vs  2048 FFMA x 2 = 4096 cyc/SMSP.
// FFMA lane map rows 96+lr+4rr, cols fw*64+cc*8+lc -> conflict-free LDS.
// ---------------------------------------------------------------------------
#define SM_WH0  0
#define SM_WH1  5120
#define SM_W0   10240
#define SM_W1   12800
#define SM_F2   15360
#define SM_E2   17408
#define SM_F1   21504
#define SM_DEN  21632
#define ATTN_SMEM_F 21760

__global__ __launch_bounds__(512, 1) void attn_mma(const int* __restrict__ adj,
                                                   float* __restrict__ out) {
    extern __shared__ float smem[];
    float*  f2s  = smem + SM_F2;
    float2* e2s  = (float2*)(smem + SM_E2);
    float*  f1s  = smem + SM_F1;
    float*  dens = smem + SM_DEN;

    const int tid  = threadIdx.x;
    const int warp = tid >> 5;
    const int lane = tid & 31;
    const bool ffw = (warp >= 12);     // FFMA warps
    const int mw   = warp >> 2;        // tensor: 0..2
    const int nw   = warp & 3;
    const int g    = lane >> 2;
    const int t    = lane & 3;
    const int fw   = warp & 3;         // FFMA warp col group
    const int lr   = lane >> 3;        // FFMA: row lane group (0..3)
    const int lc   = lane & 7;         // FFMA: col lane group (0..7)
    const int b    = blockIdx.y;
    const int i0   = blockIdx.x * 128;

    {
        const float4* f2g = (const float4*)(g_f2 + b * NN);
        ((float4*)f2s)[tid] = f2g[tid];
        const float4* e2g = (const float4*)(g_e2 + b * NN);
        ((float4*)e2s)[tid]       = e2g[tid];
        ((float4*)e2s)[tid + 512] = e2g[tid + 512];
        if (tid < 128) f1s[tid] = g_f1[b * NN + i0 + tid];
    }

    const int    r    = tid >> 2;
    const int    jq   = tid & 3;
    const int4*  arow = (const int4*)(adj + ((size_t)(b * NN + i0 + r)) * NN + jq * 8);
    const float2 e1   = g_e1[b * NN + i0 + r];
    const __half* whTsrc = g_WhT + (size_t)b * FOUT * NN;

    const float M2p  = __uint_as_float(g_m2bits[b * 2 + 0]);
    const float M2n  = __uint_as_float(g_m2bits[b * 2 + 1]);
    const float sinv = 1.f / fmaxf(e1.x * M2p, e1.y * M2n);
    const float c1p  = e1.x * sinv;
    const float c1n  = e1.y * sinv;

    const int cpn = tid >> 2;
    const int cpc = tid & 3;
    const uint32_t smem_base = (uint32_t)__cvta_generic_to_shared(smem);

    // tensor accumulators (warps 0-11) / FFMA accumulators (warps 12-15)
    float acc[2][8][4];
#pragma unroll
    for (int fm = 0; fm < 2; fm++)
#pragma unroll
        for (int fn = 0; fn < 8; fn++)
#pragma unroll
            for (int c = 0; c < 4; c++) acc[fm][fn][c] = 0.f;
    // FFMA path reuses the same 64 registers via a flat view
    float* accw = &acc[0][0][0];   // [rr][cc] = accw[rr*8+cc]

    {
#pragma unroll
        for (int p = 0; p < 2; p++) {
            int n = cpn + 128 * p;
            const __half* src = whTsrc + (size_t)n * NN + cpc * 8;
            uint32_t dst = smem_base + (SM_WH0 + n * 20 + cpc * 4) * 4;
            cp_async16(dst, src);
        }
        CP_COMMIT();
    }

    __syncthreads();
    const float f1v = f1s[r];
    float den = 0.f;

    int4 avA = arow[0];
    int4 avB = arow[1];

    for (int tt = 0; tt < 64; tt++) {
        const int cur = tt & 1;
        const int j0  = tt * 32;

        {
            int am[8] = {avA.x, avA.y, avA.z, avA.w, avB.x, avB.y, avB.z, avB.w};
            const float*  f2p = f2s + j0 + jq * 8;
            const float2* e2p = e2s + j0 + jq * 8;
            float wv[8];
#pragma unroll
            for (int u = 0; u < 8; u++) {
                float  e  = f1v + f2p[u];
                float2 e2 = e2p[u];
                float  w  = (e > 0.f) ? c1p * e2.x : c1n * e2.y;
                wv[u] = (am[u] > 0) ? w : 0.f;
            }
            uint32_t pk[4];
#pragma unroll
            for (int i = 0; i < 4; i++) {
                __half2 hp = __floats2half2_rn(wv[2 * i], wv[2 * i + 1]);
                pk[i] = *(uint32_t*)&hp;
                float2 hf = __half22float2(hp);
                den += hf.x + hf.y;
            }
            float* wd = smem + (cur ? SM_W1 : SM_W0) + r * 20 + jq * 4;
            *(float4*)wd = make_float4(__uint_as_float(pk[0]), __uint_as_float(pk[1]),
                                       __uint_as_float(pk[2]), __uint_as_float(pk[3]));
        }
        if (tt < 63) {
            avA = arow[(tt + 1) * 8];
            avB = arow[(tt + 1) * 8 + 1];
#pragma unroll
            for (int p = 0; p < 2; p++) {
                int n = cpn + 128 * p;
                const __half* src = whTsrc + (size_t)n * NN + (tt + 1) * 32 + cpc * 8;
                uint32_t dst = smem_base +
                    ((cur ? SM_WH0 : SM_WH1) + n * 20 + cpc * 4) * 4;
                cp_async16(dst, src);
            }
            CP_COMMIT();
            CP_WAIT(1);
        } else {
            CP_WAIT(0);
        }
        __syncthreads();

        const float* w_s = smem + (cur ? SM_W1 : SM_W0);
        const float* B_s = smem + (cur ? SM_WH1 : SM_WH0);

        if (!ffw) {
            // ---- tensor path: rows mw*32 .. mw*32+31 (mw 0..2) ----
#pragma unroll
            for (int fk = 0; fk < 2; fk++) {
                uint32_t A[2][4];
#pragma unroll
                for (int fm = 0; fm < 2; fm++) {
                    const float* wa = w_s + (mw * 32 + fm * 16 + g) * 20 + fk * 8 + t;
                    A[fm][0] = __float_as_uint(wa[0]);
                    A[fm][1] = __float_as_uint(wa[160]);
                    A[fm][2] = __float_as_uint(wa[4]);
                    A[fm][3] = __float_as_uint(wa[164]);
                }
#pragma unroll
                for (int fn = 0; fn < 8; fn++) {
                    const float* wb = B_s + (nw * 64 + fn * 8 + g) * 20 + fk * 8 + t;
                    uint32_t b0 = __float_as_uint(wb[0]);
                    uint32_t b1 = __float_as_uint(wb[4]);
                    mma_f16(acc[0][fn], A[0], b0, b1);
                    mma_f16(acc[1][fn], A[1], b0, b1);
                }
            }
        } else {
            // ---- FFMA path: rows 96+lr+4rr, cols fw*64+cc*8+lc ----
            const float* wr = w_s + (96 + lr) * 20;
            const float* vr = B_s + (fw * 64 + lc) * 20;
#pragma unroll 1
            for (int s = 0; s < 16; s++) {
                float2 wv2[8];
#pragma unroll
                for (int rr = 0; rr < 8; rr++)
                    wv2[rr] = __half22float2(*(const __half2*)&wr[rr * 80 + s]);
                float2 vv2[8];
#pragma unroll
                for (int cc = 0; cc < 8; cc++)
                    vv2[cc] = __half22float2(*(const __half2*)&vr[cc * 160 + s]);
#pragma unroll
                for (int rr = 0; rr < 8; rr++)
#pragma unroll
                    for (int cc = 0; cc < 8; cc++) {
                        float a = accw[rr * 8 + cc];
                        a += wv2[rr].x * vv2[cc].x;
                        a += wv2[rr].y * vv2[cc].y;
                        accw[rr * 8 + cc] = a;
                    }
            }
        }
        __syncthreads();
    }

    den += __shfl_xor_sync(0xFFFFFFFFu, den, 1);
    den += __shfl_xor_sync(0xFFFFFFFFu, den, 2);
    if (jq == 0) dens[r] = den;
    __syncthreads();

    if (!ffw) {
        // tensor epilogue: rows 0..95
#pragma unroll
        for (int fm = 0; fm < 2; fm++) {
            int row0 = mw * 32 + fm * 16 + g;
            float inv0 = 1.f / dens[row0];
            float inv1 = 1.f / dens[row0 + 8];
            float* o0 = out + ((size_t)(b * NN + i0 + row0)) * FOUT;
            float* o1 = out + ((size_t)(b * NN + i0 + row0 + 8)) * FOUT;
#pragma unroll
            for (int fn = 0; fn < 8; fn++) {
                int col = nw * 64 + fn * 8 + t * 2;
                float x0 = acc[0][fn][0 + 2 * fm * 0]; // placeholder avoided below
                (void)x0;
                float y0 = acc[fm][fn][0] * inv0;
                float y1 = acc[fm][fn][1] * inv0;
                float y2 = acc[fm][fn][2] * inv1;
                float y3 = acc[fm][fn][3] * inv1;
                float2 v0, v1;
                v0.x = y0 > 0.f ? y0 : expm1f(y0);
                v0.y = y1 > 0.f ? y1 : expm1f(y1);
                v1.x = y2 > 0.f ? y2 : expm1f(y2);
                v1.y = y3 > 0.f ? y3 : expm1f(y3);
                *(float2*)&o0[col] = v0;
                *(float2*)&o1[col] = v1;
            }
        }
    } else {
        // FFMA epilogue: rows 96..127
#pragma unroll
        for (int rr = 0; rr < 8; rr++) {
            int row = 96 + lr + rr * 4;
            float inv = 1.f / dens[row];
            float* orow = out + ((size_t)(b * NN + i0 + row)) * FOUT;
#pragma unroll
            for (int cc = 0; cc < 8; cc++) {
                int col = fw * 64 + cc * 8 + lc;
                float x = accw[rr * 8 + cc] * inv;
                orow[col] = x > 0.f ? x : expm1f(x);
            }
        }
    }
}

// ---------------------------------------------------------------------------
extern "C" void kernel_launch(void* const* d_in, const int* in_sizes, int n_in,
                              void* d_out, int out_size) {
    const float* h   = (const float*)d_in[0];
    const int*   adj = (const int*)d_in[1];
    const float* W   = (const float*)d_in[2];
    const float* a   = (const float*)d_in[3];
    float*       out = (float*)d_out;

    cudaFuncSetAttribute(wh_tc, cudaFuncAttributeMaxDynamicSharedMemorySize,
                         WH_SMEM_F * 4);
    cudaFuncSetAttribute(attn_mma, cudaFuncAttributeMaxDynamicSharedMemorySize,
                         ATTN_SMEM_F * 4);

    wt_kernel<<<dim3(FIN / 32, FOUT / 32), 256>>>(W);
    wh_tc<<<(BB * NN) / 64, 256, WH_SMEM_F * 4>>>(h, a);
    attn_mma<<<dim3(NN / 128, BB), 512, ATTN_SMEM_F * 4>>>(adj, out);
}

// round 14
// speedup vs baseline: 1.6963x; 1.6963x over previous
#include <cuda_runtime.h>
#include <cuda_fp16.h>
#include <math.h>
#include <stdint.h>

#define BB 8
#define NN 2048
#define FIN 512
#define FOUT 256
#define ALPHA 0.2f

// Scratch (allocation-free rule: __device__ globals)
__device__ __half   g_WT[FOUT * FIN];       // [n][k] fp16 (wh B operand)
__device__ __half   g_WhT[BB * FOUT * NN];  // [b][n][j] fp16 (attn B operand)
__device__ float    g_f1[BB * NN];
__device__ float    g_f2[BB * NN];
__device__ float2   g_e1[BB * NN];          // {exp(f1), exp(ALPHA*f1)}
__device__ float2   g_e2[BB * NN];          // {exp(f2), exp(ALPHA*f2)}
__device__ unsigned g_m2bits[BB * 2];       // per-batch max e2p/e2n bits (idempotent)

// ---------------------------------------------------------------------------
// mma.sync + cp.async helpers (sm_80 baseline — PTX target-safe)
// ---------------------------------------------------------------------------
__device__ __forceinline__ void mma_f16(float d[4], const uint32_t a[4],
                                        uint32_t b0, uint32_t b1) {
    asm volatile(
        "mma.sync.aligned.m16n8k16.row.col.f32.f16.f16.f32 "
        "{%0,%1,%2,%3}, {%4,%5,%6,%7}, {%8,%9}, {%0,%1,%2,%3};"
        : "+f"(d[0]), "+f"(d[1]), "+f"(d[2]), "+f"(d[3])
        : "r"(a[0]), "r"(a[1]), "r"(a[2]), "r"(a[3]), "r"(b0), "r"(b1));
}
__device__ __forceinline__ void cp_async16(uint32_t dst_smem, const void* src) {
    asm volatile("cp.async.cg.shared.global [%0], [%1], 16;"
                 :: "r"(dst_smem), "l"(src));
}
#define CP_COMMIT() asm volatile("cp.async.commit_group;" ::: "memory")
#define CP_WAIT(n)  asm volatile("cp.async.wait_group %0;" :: "n"(n) : "memory")
__device__ __forceinline__ uint32_t h2bits(float x, float y) {
    __half2 h = __floats2half2_rn(x, y);
    return *(uint32_t*)&h;
}

// ---------------------------------------------------------------------------
// Kernel 0: W [k][n] fp32 -> g_WT [n][k] fp16 (tiled transpose, tiny)
// ---------------------------------------------------------------------------
__global__ __launch_bounds__(256) void wt_kernel(const float* __restrict__ W) {
    __shared__ float tile[32][33];
    const int k0 = blockIdx.x * 32;
    const int n0 = blockIdx.y * 32;
    const int tx = threadIdx.x & 31, ty = threadIdx.x >> 5;
#pragma unroll
    for (int i = 0; i < 32; i += 8)
        tile[ty + i][tx] = W[(size_t)(k0 + ty + i) * FOUT + n0 + tx];
    __syncthreads();
#pragma unroll
    for (int i = 0; i < 32; i += 8)
        g_WT[(size_t)(n0 + ty + i) * FIN + k0 + tx] = __float2half_rn(tile[tx][ty + i]);
}

// ---------------------------------------------------------------------------
// Kernel 1: Wh = h @ W, fp16 m16n8k16 (fp32 acc), fused f1/f2/exp epilogue.
// (R11 version — unchanged)
// ---------------------------------------------------------------------------
#define WH_AS  0
#define WH_BS  1280
#define WH_SA  6400
#define WH_F1P 6912
#define WH_F2P 7168
#define WH_SMEM_F 7424

__global__ __launch_bounds__(256, 2) void wh_tc(const float* __restrict__ h,
                                                const float* __restrict__ aa) {
    extern __shared__ float sm[];
    float* A_s  = sm + WH_AS;
    float* B_s  = sm + WH_BS;
    float* sA   = sm + WH_SA;
    float* f1p  = sm + WH_F1P;
    float* f2p  = sm + WH_F2P;

    const int tid  = threadIdx.x;
    const int warp = tid >> 5;
    const int lane = tid & 31;
    const int mw   = warp >> 2;
    const int nw   = warp & 3;
    const int g    = lane >> 2;
    const int t    = lane & 3;
    const int row0 = blockIdx.x * 64;

    sA[tid]       = aa[tid];
    sA[tid + 256] = aa[tid + 256];

    float acc[2][8][4];
#pragma unroll
    for (int fm = 0; fm < 2; fm++)
#pragma unroll
        for (int fn = 0; fn < 8; fn++)
#pragma unroll
            for (int c = 0; c < 4; c++) acc[fm][fn][c] = 0.f;

    const int r  = tid >> 2, q = tid & 3;
    const int bn = tid >> 2;
    const int bc = tid & 3;
    const uint32_t smem_base = (uint32_t)__cvta_generic_to_shared(sm);

    for (int k0 = 0; k0 < FIN; k0 += 32) {
        {
            const float* src = h + (size_t)(row0 + r) * FIN + k0 + q * 8;
            float4 v0 = *(const float4*)src;
            float4 v1 = *(const float4*)(src + 4);
            float* ad = A_s + r * 20 + q * 4;
            ad[0] = __uint_as_float(h2bits(v0.x, v0.y));
            ad[1] = __uint_as_float(h2bits(v0.z, v0.w));
            ad[2] = __uint_as_float(h2bits(v1.x, v1.y));
            ad[3] = __uint_as_float(h2bits(v1.z, v1.w));
        }
#pragma unroll
        for (int p = 0; p < 4; p++) {
            int n = bn + 64 * p;
            const __half* src = g_WT + (size_t)n * FIN + k0 + bc * 8;
            uint32_t dst = smem_base + (WH_BS + n * 20 + bc * 4) * 4;
            cp_async16(dst, src);
        }
        CP_COMMIT();
        CP_WAIT(0);
        __syncthreads();

#pragma unroll
        for (int fk = 0; fk < 2; fk++) {
            uint32_t A[2][4];
#pragma unroll
            for (int fm = 0; fm < 2; fm++) {
                const float* wa = A_s + (mw * 32 + fm * 16 + g) * 20 + fk * 8 + t;
                A[fm][0] = __float_as_uint(wa[0]);
                A[fm][1] = __float_as_uint(wa[160]);
                A[fm][2] = __float_as_uint(wa[4]);
                A[fm][3] = __float_as_uint(wa[164]);
            }
#pragma unroll
            for (int fn = 0; fn < 8; fn++) {
                const float* wb = B_s + (nw * 64 + fn * 8 + g) * 20 + fk * 8 + t;
                uint32_t b0 = __float_as_uint(wb[0]);
                uint32_t b1 = __float_as_uint(wb[4]);
                mma_f16(acc[0][fn], A[0], b0, b1);
                mma_f16(acc[1][fn], A[1], b0, b1);
            }
        }
        __syncthreads();
    }

#pragma unroll
    for (int fm = 0; fm < 2; fm++) {
        int rr = row0 + mw * 32 + fm * 16 + g;
        int bb = rr >> 11;
        int jj = rr & (NN - 1);
#pragma unroll
        for (int fn = 0; fn < 8; fn++) {
            int col = nw * 64 + fn * 8 + t * 2;
            size_t base = ((size_t)bb * FOUT + col) * NN + jj;
            g_WhT[base]          = __float2half_rn(acc[fm][fn][0]);
            g_WhT[base + NN]     = __float2half_rn(acc[fm][fn][1]);
            g_WhT[base + 8]      = __float2half_rn(acc[fm][fn][2]);
            g_WhT[base + NN + 8] = __float2half_rn(acc[fm][fn][3]);
        }
    }

    {
        float p1[4] = {0.f, 0.f, 0.f, 0.f};
        float p2[4] = {0.f, 0.f, 0.f, 0.f};
#pragma unroll
        for (int fm = 0; fm < 2; fm++)
#pragma unroll
            for (int fn = 0; fn < 8; fn++) {
                int col = nw * 64 + fn * 8 + t * 2;
                float a10 = sA[col], a11 = sA[col + 1];
                float a20 = sA[256 + col], a21 = sA[256 + col + 1];
                p1[fm * 2 + 0] += acc[fm][fn][0] * a10 + acc[fm][fn][1] * a11;
                p1[fm * 2 + 1] += acc[fm][fn][2] * a10 + acc[fm][fn][3] * a11;
                p2[fm * 2 + 0] += acc[fm][fn][0] * a20 + acc[fm][fn][1] * a21;
                p2[fm * 2 + 1] += acc[fm][fn][2] * a20 + acc[fm][fn][3] * a21;
            }
#pragma unroll
        for (int off = 1; off <= 2; off <<= 1)
#pragma unroll
            for (int i = 0; i < 4; i++) {
                p1[i] += __shfl_xor_sync(0xFFFFFFFFu, p1[i], off);
                p2[i] += __shfl_xor_sync(0xFFFFFFFFu, p2[i], off);
            }
        if (t == 0) {
#pragma unroll
            for (int fm = 0; fm < 2; fm++)
#pragma unroll
                for (int hi = 0; hi < 2; hi++) {
                    int rowl = mw * 32 + fm * 16 + g + hi * 8;
                    f1p[rowl * 4 + nw] = p1[fm * 2 + hi];
                    f2p[rowl * 4 + nw] = p2[fm * 2 + hi];
                }
        }
    }
    __syncthreads();
    if (tid < 64) {
        float s1 = ((f1p[tid * 4] + f1p[tid * 4 + 1]) + f1p[tid * 4 + 2]) + f1p[tid * 4 + 3];
        float s2 = ((f2p[tid * 4] + f2p[tid * 4 + 1]) + f2p[tid * 4 + 2]) + f2p[tid * 4 + 3];
        int rr = row0 + tid;
        int bb = rr >> 11;
        g_f1[rr] = s1;
        g_f2[rr] = s2;
        float e2p = __expf(s2), e2n = __expf(ALPHA * s2);
        g_e1[rr] = make_float2(__expf(s1), __expf(ALPHA * s1));
        g_e2[rr] = make_float2(e2p, e2n);
        atomicMax(&g_m2bits[bb * 2 + 0], __float_as_uint(e2p));
        atomicMax(&g_m2bits[bb * 2 + 1], __float_as_uint(e2n));
    }
}

// ---------------------------------------------------------------------------
// Kernel 2: fused masked-softmax aggregation, fp16 m16n8k16 (fp32 acc).
// SINGLE-BARRIER software pipeline: per iter, issue MMAs(tt) first, then
// fill w(tt+1) + cp.async WhT(tt+2) (4-buffer rotation, depth 2), one
// CP_WAIT(1) + one __syncthreads. Fill hides in HMMA backpressure gaps.
// Arithmetic identical to R11.
// ---------------------------------------------------------------------------
#define SM_WH   0                      // 4 bufs x 5120 = 20480 floats
#define SM_W    20480                  // 2 bufs x 2560 = 5120
#define SM_F2   25600                  // 2048
#define SM_E2   27648                  // 4096
#define SM_F1   31744                  // 128
#define SM_DEN  31872                  // 128
#define ATTN_SMEM_F 32000              // 128000 B

__global__ __launch_bounds__(512, 1) void attn_mma(const int* __restrict__ adj,
                                                   float* __restrict__ out) {
    extern __shared__ float smem[];
    float*  f2s  = smem + SM_F2;
    float2* e2s  = (float2*)(smem + SM_E2);
    float*  f1s  = smem + SM_F1;
    float*  dens = smem + SM_DEN;

    const int tid  = threadIdx.x;
    const int warp = tid >> 5;
    const int lane = tid & 31;
    const int mw   = warp >> 2;
    const int nw   = warp & 3;
    const int g    = lane >> 2;
    const int t    = lane & 3;
    const int b    = blockIdx.y;
    const int i0   = blockIdx.x * 128;

    {
        const float4* f2g = (const float4*)(g_f2 + b * NN);
        ((float4*)f2s)[tid] = f2g[tid];
        const float4* e2g = (const float4*)(g_e2 + b * NN);
        ((float4*)e2s)[tid]       = e2g[tid];
        ((float4*)e2s)[tid + 512] = e2g[tid + 512];
        if (tid < 128) f1s[tid] = g_f1[b * NN + i0 + tid];
    }

    const int    r    = tid >> 2;
    const int    jq   = tid & 3;
    const int4*  arow = (const int4*)(adj + ((size_t)(b * NN + i0 + r)) * NN + jq * 8);
    const float2 e1   = g_e1[b * NN + i0 + r];
    const __half* whTsrc = g_WhT + (size_t)b * FOUT * NN;

    const float M2p  = __uint_as_float(g_m2bits[b * 2 + 0]);
    const float M2n  = __uint_as_float(g_m2bits[b * 2 + 1]);
    const float sinv = 1.f / fmaxf(e1.x * M2p, e1.y * M2n);
    const float c1p  = e1.x * sinv;
    const float c1n  = e1.y * sinv;

    const int cpn = tid >> 2;
    const int cpc = tid & 3;
    const uint32_t smem_base = (uint32_t)__cvta_generic_to_shared(smem);

    float acc[2][8][4];
#pragma unroll
    for (int fm = 0; fm < 2; fm++)
#pragma unroll
        for (int fn = 0; fn < 8; fn++)
#pragma unroll
            for (int c = 0; c < 4; c++) acc[fm][fn][c] = 0.f;

    // prologue: cp.async WhT tiles 0,1 into bufs 0,1 (two groups)
#pragma unroll
    for (int tpre = 0; tpre < 2; tpre++) {
#pragma unroll
        for (int p = 0; p < 2; p++) {
            int n = cpn + 128 * p;
            const __half* src = whTsrc + (size_t)n * NN + tpre * 32 + cpc * 8;
            uint32_t dst = smem_base + (SM_WH + tpre * 5120 + n * 20 + cpc * 4) * 4;
            cp_async16(dst, src);
        }
        CP_COMMIT();
    }

    __syncthreads();              // tables staged
    const float f1v = f1s[r];
    float den = 0.f;

    // helper values for w fill
    // prologue: fill w(0) into wbuf0 (direct adj load), prefetch adj(1)
    int4 avA, avB;
    {
        int4 a0 = arow[0], b0v = arow[1];
        int am[8] = {a0.x, a0.y, a0.z, a0.w, b0v.x, b0v.y, b0v.z, b0v.w};
        const float*  f2p = f2s + jq * 8;
        const float2* e2p = e2s + jq * 8;
        float wv[8];
#pragma unroll
        for (int u = 0; u < 8; u++) {
            float  e  = f1v + f2p[u];
            float2 e2 = e2p[u];
            float  w  = (e > 0.f) ? c1p * e2.x : c1n * e2.y;
            wv[u] = (am[u] > 0) ? w : 0.f;
        }
        uint32_t pk[4];
#pragma unroll
        for (int i = 0; i < 4; i++) {
            __half2 hp = __floats2half2_rn(wv[2 * i], wv[2 * i + 1]);
            pk[i] = *(uint32_t*)&hp;
            float2 hf = __half22float2(hp);
            den += hf.x + hf.y;
        }
        float* wd = smem + SM_W + r * 20 + jq * 4;
        *(float4*)wd = make_float4(__uint_as_float(pk[0]), __uint_as_float(pk[1]),
                                   __uint_as_float(pk[2]), __uint_as_float(pk[3]));
        avA = arow[8];
        avB = arow[9];
    }
    CP_WAIT(1);                   // tile 0 arrived
    __syncthreads();              // w(0) + WhT(0) visible

    for (int tt = 0; tt < 64; tt++) {
        const float* w_s = smem + SM_W + (tt & 1) * 2560;
        const float* B_s = smem + SM_WH + (tt & 3) * 5120;

        // ---- MMA phase for tile tt (issued first; pipe churns below) ----
#pragma unroll
        for (int fk = 0; fk < 2; fk++) {
            uint32_t A[2][4];
#pragma unroll
            for (int fm = 0; fm < 2; fm++) {
                const float* wa = w_s + (mw * 32 + fm * 16 + g) * 20 + fk * 8 + t;
                A[fm][0] = __float_as_uint(wa[0]);
                A[fm][1] = __float_as_uint(wa[160]);
                A[fm][2] = __float_as_uint(wa[4]);
                A[fm][3] = __float_as_uint(wa[164]);
            }
#pragma unroll
            for (int fn = 0; fn < 8; fn++) {
                const float* wb = B_s + (nw * 64 + fn * 8 + g) * 20 + fk * 8 + t;
                uint32_t b0 = __float_as_uint(wb[0]);
                uint32_t b1 = __float_as_uint(wb[4]);
                mma_f16(acc[0][fn], A[0], b0, b1);
                mma_f16(acc[1][fn], A[1], b0, b1);
            }
        }

        // ---- fill w(tt+1) into other w-buffer (issues under MMA churn) ----
        if (tt < 63) {
            const int jn = (tt + 1) * 32;
            int am[8] = {avA.x, avA.y, avA.z, avA.w, avB.x, avB.y, avB.z, avB.w};
            const float*  f2p = f2s + jn + jq * 8;
            const float2* e2p = e2s + jn + jq * 8;
            float wv[8];
#pragma unroll
            for (int u = 0; u < 8; u++) {
                float  e  = f1v + f2p[u];
                float2 e2 = e2p[u];
                float  w  = (e > 0.f) ? c1p * e2.x : c1n * e2.y;
                wv[u] = (am[u] > 0) ? w : 0.f;
            }
            uint32_t pk[4];
#pragma unroll
            for (int i = 0; i < 4; i++) {
                __half2 hp = __floats2half2_rn(wv[2 * i], wv[2 * i + 1]);
                pk[i] = *(uint32_t*)&hp;
                float2 hf = __half22float2(hp);
                den += hf.x + hf.y;
            }
            float* wd = smem + SM_W + ((tt + 1) & 1) * 2560 + r * 20 + jq * 4;
            *(float4*)wd = make_float4(__uint_as_float(pk[0]), __uint_as_float(pk[1]),
                                       __uint_as_float(pk[2]), __uint_as_float(pk[3]));
            if (tt < 62) {
                avA = arow[(tt + 2) * 8];
                avB = arow[(tt + 2) * 8 + 1];
            }
        }
        // ---- cp.async WhT(tt+2) into buf (tt+2)&3 ----
        if (tt < 62) {
#pragma unroll
            for (int p = 0; p < 2; p++) {
                int n = cpn + 128 * p;
                const __half* src = whTsrc + (size_t)n * NN + (tt + 2) * 32 + cpc * 8;
                uint32_t dst = smem_base +
                    (SM_WH + ((tt + 2) & 3) * 5120 + n * 20 + cpc * 4) * 4;
                cp_async16(dst, src);
            }
        }
        CP_COMMIT();              // unconditional: keeps group count uniform
        CP_WAIT(1);               // tile tt+1 arrived (FIFO group order)
        __syncthreads();
    }

    den += __shfl_xor_sync(0xFFFFFFFFu, den, 1);
    den += __shfl_xor_sync(0xFFFFFFFFu, den, 2);
    if (jq == 0) dens[r] = den;
    __syncthreads();

#pragma unroll
    for (int fm = 0; fm < 2; fm++) {
        int row0 = mw * 32 + fm * 16 + g;
        float inv0 = 1.f / dens[row0];
        float inv1 = 1.f / dens[row0 + 8];
        float* o0 = out + ((size_t)(b * NN + i0 + row0)) * FOUT;
        float* o1 = out + ((size_t)(b * NN + i0 + row0 + 8)) * FOUT;
#pragma unroll
        for (int fn = 0; fn < 8; fn++) {
            int col = nw * 64 + fn * 8 + t * 2;
            float x0 = acc[fm][fn][0] * inv0;
            float x1 = acc[fm][fn][1] * inv0;
            float x2 = acc[fm][fn][2] * inv1;
            float x3 = acc[fm][fn][3] * inv1;
            float2 v0, v1;
            v0.x = x0 > 0.f ? x0 : expm1f(x0);
            v0.y = x1 > 0.f ? x1 : expm1f(x1);
            v1.x = x2 > 0.f ? x2 : expm1f(x2);
            v1.y = x3 > 0.f ? x3 : expm1f(x3);
            *(float2*)&o0[col] = v0;
            *(float2*)&o1[col] = v1;
        }
    }
}

// ---------------------------------------------------------------------------
extern "C" void kernel_launch(void* const* d_in, const int* in_sizes, int n_in,
                              void* d_out, int out_size) {
    const float* h   = (const float*)d_in[0];
    const int*   adj = (const int*)d_in[1];
    const float* W   = (const float*)d_in[2];
    const float* a   = (const float*)d_in[3];
    float*       out = (float*)d_out;

    cudaFuncSetAttribute(wh_tc, cudaFuncAttributeMaxDynamicSharedMemorySize,
                         WH_SMEM_F * 4);
    cudaFuncSetAttribute(attn_mma, cudaFuncAttributeMaxDynamicSharedMemorySize,
                         ATTN_SMEM_F * 4);

    wt_kernel<<<dim3(FIN / 32, FOUT / 32), 256>>>(W);
    wh_tc<<<(BB * NN) / 64, 256, WH_SMEM_F * 4>>>(h, a);
    attn_mma<<<dim3(NN / 128, BB), 512, ATTN_SMEM_F * 4>>>(adj, out);
}

// round 15
// speedup vs baseline: 1.7244x; 1.0165x over previous
#include <cuda_runtime.h>
#include <cuda_fp16.h>
#include <math.h>
#include <stdint.h>

#define BB 8
#define NN 2048
#define FIN 512
#define FOUT 256
#define ALPHA 0.2f

// Scratch (allocation-free rule: __device__ globals)
__device__ __half   g_WT[FOUT * FIN];       // [n][k] fp16 (wh B operand)
__device__ __half   g_WhT[BB * FOUT * NN];  // [b][n][j] fp16 (attn B operand)
__device__ float    g_f1[BB * NN];
__device__ float    g_f2[BB * NN];
__device__ float2   g_e1[BB * NN];          // {exp(f1), exp(ALPHA*f1)}
__device__ float2   g_e2[BB * NN];          // {exp(f2), exp(ALPHA*f2)}
__device__ unsigned g_m2bits[BB * 2];       // per-batch max e2p/e2n bits (idempotent)

// ---------------------------------------------------------------------------
// mma.sync + cp.async helpers (sm_80 baseline — PTX target-safe)
// ---------------------------------------------------------------------------
__device__ __forceinline__ void mma_f16(float d[4], const uint32_t a[4],
                                        uint32_t b0, uint32_t b1) {
    asm volatile(
        "mma.sync.aligned.m16n8k16.row.col.f32.f16.f16.f32 "
        "{%0,%1,%2,%3}, {%4,%5,%6,%7}, {%8,%9}, {%0,%1,%2,%3};"
        : "+f"(d[0]), "+f"(d[1]), "+f"(d[2]), "+f"(d[3])
        : "r"(a[0]), "r"(a[1]), "r"(a[2]), "r"(a[3]), "r"(b0), "r"(b1));
}
__device__ __forceinline__ void cp_async16(uint32_t dst_smem, const void* src) {
    asm volatile("cp.async.cg.shared.global [%0], [%1], 16;"
                 :: "r"(dst_smem), "l"(src));
}
#define CP_COMMIT() asm volatile("cp.async.commit_group;" ::: "memory")
#define CP_WAIT(n)  asm volatile("cp.async.wait_group %0;" :: "n"(n) : "memory")
__device__ __forceinline__ uint32_t h2bits(float x, float y) {
    __half2 h = __floats2half2_rn(x, y);
    return *(uint32_t*)&h;
}

// ---------------------------------------------------------------------------
// Kernel 0: W [k][n] fp32 -> g_WT [n][k] fp16 (tiled transpose, tiny)
// ---------------------------------------------------------------------------
__global__ __launch_bounds__(256) void wt_kernel(const float* __restrict__ W) {
    __shared__ float tile[32][33];
    const int k0 = blockIdx.x * 32;
    const int n0 = blockIdx.y * 32;
    const int tx = threadIdx.x & 31, ty = threadIdx.x >> 5;
#pragma unroll
    for (int i = 0; i < 32; i += 8)
        tile[ty + i][tx] = W[(size_t)(k0 + ty + i) * FOUT + n0 + tx];
    __syncthreads();
#pragma unroll
    for (int i = 0; i < 32; i += 8)
        g_WT[(size_t)(n0 + ty + i) * FIN + k0 + tx] = __float2half_rn(tile[tx][ty + i]);
}

// ---------------------------------------------------------------------------
// Kernel 1: Wh = h @ W, fp16 m16n8k16 (fp32 acc), fused f1/f2/exp epilogue.
// (R11 version — unchanged)
// ---------------------------------------------------------------------------
#define WH_AS  0
#define WH_BS  1280
#define WH_SA  6400
#define WH_F1P 6912
#define WH_F2P 7168
#define WH_SMEM_F 7424

__global__ __launch_bounds__(256, 2) void wh_tc(const float* __restrict__ h,
                                                const float* __restrict__ aa) {
    extern __shared__ float sm[];
    float* A_s  = sm + WH_AS;
    float* B_s  = sm + WH_BS;
    float* sA   = sm + WH_SA;
    float* f1p  = sm + WH_F1P;
    float* f2p  = sm + WH_F2P;

    const int tid  = threadIdx.x;
    const int warp = tid >> 5;
    const int lane = tid & 31;
    const int mw   = warp >> 2;
    const int nw   = warp & 3;
    const int g    = lane >> 2;
    const int t    = lane & 3;
    const int row0 = blockIdx.x * 64;

    sA[tid]       = aa[tid];
    sA[tid + 256] = aa[tid + 256];

    float acc[2][8][4];
#pragma unroll
    for (int fm = 0; fm < 2; fm++)
#pragma unroll
        for (int fn = 0; fn < 8; fn++)
#pragma unroll
            for (int c = 0; c < 4; c++) acc[fm][fn][c] = 0.f;

    const int r  = tid >> 2, q = tid & 3;
    const int bn = tid >> 2;
    const int bc = tid & 3;
    const uint32_t smem_base = (uint32_t)__cvta_generic_to_shared(sm);

    for (int k0 = 0; k0 < FIN; k0 += 32) {
        {
            const float* src = h + (size_t)(row0 + r) * FIN + k0 + q * 8;
            float4 v0 = *(const float4*)src;
            float4 v1 = *(const float4*)(src + 4);
            float* ad = A_s + r * 20 + q * 4;
            ad[0] = __uint_as_float(h2bits(v0.x, v0.y));
            ad[1] = __uint_as_float(h2bits(v0.z, v0.w));
            ad[2] = __uint_as_float(h2bits(v1.x, v1.y));
            ad[3] = __uint_as_float(h2bits(v1.z, v1.w));
        }
#pragma unroll
        for (int p = 0; p < 4; p++) {
            int n = bn + 64 * p;
            const __half* src = g_WT + (size_t)n * FIN + k0 + bc * 8;
            uint32_t dst = smem_base + (WH_BS + n * 20 + bc * 4) * 4;
            cp_async16(dst, src);
        }
        CP_COMMIT();
        CP_WAIT(0);
        __syncthreads();

#pragma unroll
        for (int fk = 0; fk < 2; fk++) {
            uint32_t A[2][4];
#pragma unroll
            for (int fm = 0; fm < 2; fm++) {
                const float* wa = A_s + (mw * 32 + fm * 16 + g) * 20 + fk * 8 + t;
                A[fm][0] = __float_as_uint(wa[0]);
                A[fm][1] = __float_as_uint(wa[160]);
                A[fm][2] = __float_as_uint(wa[4]);
                A[fm][3] = __float_as_uint(wa[164]);
            }
#pragma unroll
            for (int fn = 0; fn < 8; fn++) {
                const float* wb = B_s + (nw * 64 + fn * 8 + g) * 20 + fk * 8 + t;
                uint32_t b0 = __float_as_uint(wb[0]);
                uint32_t b1 = __float_as_uint(wb[4]);
                mma_f16(acc[0][fn], A[0], b0, b1);
                mma_f16(acc[1][fn], A[1], b0, b1);
            }
        }
        __syncthreads();
    }

#pragma unroll
    for (int fm = 0; fm < 2; fm++) {
        int rr = row0 + mw * 32 + fm * 16 + g;
        int bb = rr >> 11;
        int jj = rr & (NN - 1);
#pragma unroll
        for (int fn = 0; fn < 8; fn++) {
            int col = nw * 64 + fn * 8 + t * 2;
            size_t base = ((size_t)bb * FOUT + col) * NN + jj;
            g_WhT[base]          = __float2half_rn(acc[fm][fn][0]);
            g_WhT[base + NN]     = __float2half_rn(acc[fm][fn][1]);
            g_WhT[base + 8]      = __float2half_rn(acc[fm][fn][2]);
            g_WhT[base + NN + 8] = __float2half_rn(acc[fm][fn][3]);
        }
    }

    {
        float p1[4] = {0.f, 0.f, 0.f, 0.f};
        float p2[4] = {0.f, 0.f, 0.f, 0.f};
#pragma unroll
        for (int fm = 0; fm < 2; fm++)
#pragma unroll
            for (int fn = 0; fn < 8; fn++) {
                int col = nw * 64 + fn * 8 + t * 2;
                float a10 = sA[col], a11 = sA[col + 1];
                float a20 = sA[256 + col], a21 = sA[256 + col + 1];
                p1[fm * 2 + 0] += acc[fm][fn][0] * a10 + acc[fm][fn][1] * a11;
                p1[fm * 2 + 1] += acc[fm][fn][2] * a10 + acc[fm][fn][3] * a11;
                p2[fm * 2 + 0] += acc[fm][fn][0] * a20 + acc[fm][fn][1] * a21;
                p2[fm * 2 + 1] += acc[fm][fn][2] * a20 + acc[fm][fn][3] * a21;
            }
#pragma unroll
        for (int off = 1; off <= 2; off <<= 1)
#pragma unroll
            for (int i = 0; i < 4; i++) {
                p1[i] += __shfl_xor_sync(0xFFFFFFFFu, p1[i], off);
                p2[i] += __shfl_xor_sync(0xFFFFFFFFu, p2[i], off);
            }
        if (t == 0) {
#pragma unroll
            for (int fm = 0; fm < 2; fm++)
#pragma unroll
                for (int hi = 0; hi < 2; hi++) {
                    int rowl = mw * 32 + fm * 16 + g + hi * 8;
                    f1p[rowl * 4 + nw] = p1[fm * 2 + hi];
                    f2p[rowl * 4 + nw] = p2[fm * 2 + hi];
                }
        }
    }
    __syncthreads();
    if (tid < 64) {
        float s1 = ((f1p[tid * 4] + f1p[tid * 4 + 1]) + f1p[tid * 4 + 2]) + f1p[tid * 4 + 3];
        float s2 = ((f2p[tid * 4] + f2p[tid * 4 + 1]) + f2p[tid * 4 + 2]) + f2p[tid * 4 + 3];
        int rr = row0 + tid;
        int bb = rr >> 11;
        g_f1[rr] = s1;
        g_f2[rr] = s2;
        float e2p = __expf(s2), e2n = __expf(ALPHA * s2);
        g_e1[rr] = make_float2(__expf(s1), __expf(ALPHA * s1));
        g_e2[rr] = make_float2(e2p, e2n);
        atomicMax(&g_m2bits[bb * 2 + 0], __float_as_uint(e2p));
        atomicMax(&g_m2bits[bb * 2 + 1], __float_as_uint(e2n));
    }
}

// ---------------------------------------------------------------------------
// Kernel 2: fused masked-softmax aggregation, fp16 m16n8k16 (fp32 acc).
// SINGLE-BARRIER software pipeline: per iter, issue MMAs(tt) first, then
// fill w(tt+1) + cp.async WhT(tt+2) (4-buffer rotation, depth 2), one
// CP_WAIT(1) + one __syncthreads. Fill hides in HMMA backpressure gaps.
// Arithmetic identical to R11.
// ---------------------------------------------------------------------------
#define SM_WH   0                      // 4 bufs x 5120 = 20480 floats
#define SM_W    20480                  // 2 bufs x 2560 = 5120
#define SM_F2   25600                  // 2048
#define SM_E2   27648                  // 4096
#define SM_F1   31744                  // 128
#define SM_DEN  31872                  // 128
#define ATTN_SMEM_F 32000              // 128000 B

__global__ __launch_bounds__(512, 1) void attn_mma(const int* __restrict__ adj,
                                                   float* __restrict__ out) {
    extern __shared__ float smem[];
    float*  f2s  = smem + SM_F2;
    float2* e2s  = (float2*)(smem + SM_E2);
    float*  f1s  = smem + SM_F1;
    float*  dens = smem + SM_DEN;

    const int tid  = threadIdx.x;
    const int warp = tid >> 5;
    const int lane = tid & 31;
    const int mw   = warp >> 2;
    const int nw   = warp & 3;
    const int g    = lane >> 2;
    const int t    = lane & 3;
    const int b    = blockIdx.y;
    const int i0   = blockIdx.x * 128;

    {
        const float4* f2g = (const float4*)(g_f2 + b * NN);
        ((float4*)f2s)[tid] = f2g[tid];
        const float4* e2g = (const float4*)(g_e2 + b * NN);
        ((float4*)e2s)[tid]       = e2g[tid];
        ((float4*)e2s)[tid + 512] = e2g[tid + 512];
        if (tid < 128) f1s[tid] = g_f1[b * NN + i0 + tid];
    }

    const int    r    = tid >> 2;
    const int    jq   = tid & 3;
    const int4*  arow = (const int4*)(adj + ((size_t)(b * NN + i0 + r)) * NN + jq * 8);
    const float2 e1   = g_e1[b * NN + i0 + r];
    const __half* whTsrc = g_WhT + (size_t)b * FOUT * NN;

    const float M2p  = __uint_as_float(g_m2bits[b * 2 + 0]);
    const float M2n  = __uint_as_float(g_m2bits[b * 2 + 1]);
    const float sinv = 1.f / fmaxf(e1.x * M2p, e1.y * M2n);
    const float c1p  = e1.x * sinv;
    const float c1n  = e1.y * sinv;

    const int cpn = tid >> 2;
    const int cpc = tid & 3;
    const uint32_t smem_base = (uint32_t)__cvta_generic_to_shared(smem);

    float acc[2][8][4];
#pragma unroll
    for (int fm = 0; fm < 2; fm++)
#pragma unroll
        for (int fn = 0; fn < 8; fn++)
#pragma unroll
            for (int c = 0; c < 4; c++) acc[fm][fn][c] = 0.f;

    // prologue: cp.async WhT tiles 0,1 into bufs 0,1 (two groups)
#pragma unroll
    for (int tpre = 0; tpre < 2; tpre++) {
#pragma unroll
        for (int p = 0; p < 2; p++) {
            int n = cpn + 128 * p;
            const __half* src = whTsrc + (size_t)n * NN + tpre * 32 + cpc * 8;
            uint32_t dst = smem_base + (SM_WH + tpre * 5120 + n * 20 + cpc * 4) * 4;
            cp_async16(dst, src);
        }
        CP_COMMIT();
    }

    __syncthreads();              // tables staged
    const float f1v = f1s[r];
    float den = 0.f;

    // helper values for w fill
    // prologue: fill w(0) into wbuf0 (direct adj load), prefetch adj(1)
    int4 avA, avB;
    {
        int4 a0 = arow[0], b0v = arow[1];
        int am[8] = {a0.x, a0.y, a0.z, a0.w, b0v.x, b0v.y, b0v.z, b0v.w};
        const float*  f2p = f2s + jq * 8;
        const float2* e2p = e2s + jq * 8;
        float wv[8];
#pragma unroll
        for (int u = 0; u < 8; u++) {
            float  e  = f1v + f2p[u];
            float2 e2 = e2p[u];
            float  w  = (e > 0.f) ? c1p * e2.x : c1n * e2.y;
            wv[u] = (am[u] > 0) ? w : 0.f;
        }
        uint32_t pk[4];
#pragma unroll
        for (int i = 0; i < 4; i++) {
            __half2 hp = __floats2half2_rn(wv[2 * i], wv[2 * i + 1]);
            pk[i] = *(uint32_t*)&hp;
            float2 hf = __half22float2(hp);
            den += hf.x + hf.y;
        }
        float* wd = smem + SM_W + r * 20 + jq * 4;
        *(float4*)wd = make_float4(__uint_as_float(pk[0]), __uint_as_float(pk[1]),
                                   __uint_as_float(pk[2]), __uint_as_float(pk[3]));
        avA = arow[8];
        avB = arow[9];
    }
    CP_WAIT(1);                   // tile 0 arrived
    __syncthreads();              // w(0) + WhT(0) visible

    for (int tt = 0; tt < 64; tt++) {
        const float* w_s = smem + SM_W + (tt & 1) * 2560;
        const float* B_s = smem + SM_WH + (tt & 3) * 5120;

        // ---- MMA phase for tile tt (issued first; pipe churns below) ----
#pragma unroll
        for (int fk = 0; fk < 2; fk++) {
            uint32_t A[2][4];
#pragma unroll
            for (int fm = 0; fm < 2; fm++) {
                const float* wa = w_s + (mw * 32 + fm * 16 + g) * 20 + fk * 8 + t;
                A[fm][0] = __float_as_uint(wa[0]);
                A[fm][1] = __float_as_uint(wa[160]);
                A[fm][2] = __float_as_uint(wa[4]);
                A[fm][3] = __float_as_uint(wa[164]);
            }
#pragma unroll
            for (int fn = 0; fn < 8; fn++) {
                const float* wb = B_s + (nw * 64 + fn * 8 + g) * 20 + fk * 8 + t;
                uint32_t b0 = __float_as_uint(wb[0]);
                uint32_t b1 = __float_as_uint(wb[4]);
                mma_f16(acc[0][fn], A[0], b0, b1);
                mma_f16(acc[1][fn], A[1], b0, b1);
            }
        }

        // ---- fill w(tt+1) into other w-buffer (issues under MMA churn) ----
        if (tt < 63) {
            const int jn = (tt + 1) * 32;
            int am[8] = {avA.x, avA.y, avA.z, avA.w, avB.x, avB.y, avB.z, avB.w};
            const float*  f2p = f2s + jn + jq * 8;
            const float2* e2p = e2s + jn + jq * 8;
            float wv[8];
#pragma unroll
            for (int u = 0; u < 8; u++) {
                float  e  = f1v + f2p[u];
                float2 e2 = e2p[u];
                float  w  = (e > 0.f) ? c1p * e2.x : c1n * e2.y;
                wv[u] = (am[u] > 0) ? w : 0.f;
            }
            uint32_t pk[4];
#pragma unroll
            for (int i = 0; i < 4; i++) {
                __half2 hp = __floats2half2_rn(wv[2 * i], wv[2 * i + 1]);
                pk[i] = *(uint32_t*)&hp;
                float2 hf = __half22float2(hp);
                den += hf.x + hf.y;
            }
            float* wd = smem + SM_W + ((tt + 1) & 1) * 2560 + r * 20 + jq * 4;
            *(float4*)wd = make_float4(__uint_as_float(pk[0]), __uint_as_float(pk[1]),
                                       __uint_as_float(pk[2]), __uint_as_float(pk[3]));
            if (tt < 62) {
                avA = arow[(tt + 2) * 8];
                avB = arow[(tt + 2) * 8 + 1];
            }
        }
        // ---- cp.async WhT(tt+2) into buf (tt+2)&3 ----
        if (tt < 62) {
#pragma unroll
            for (int p = 0; p < 2; p++) {
                int n = cpn + 128 * p;
                const __half* src = whTsrc + (size_t)n * NN + (tt + 2) * 32 + cpc * 8;
                uint32_t dst = smem_base +
                    (SM_WH + ((tt + 2) & 3) * 5120 + n * 20 + cpc * 4) * 4;
                cp_async16(dst, src);
            }
        }
        CP_COMMIT();              // unconditional: keeps group count uniform
        CP_WAIT(1);               // tile tt+1 arrived (FIFO group order)
        __syncthreads();
    }

    den += __shfl_xor_sync(0xFFFFFFFFu, den, 1);
    den += __shfl_xor_sync(0xFFFFFFFFu, den, 2);
    if (jq == 0) dens[r] = den;
    __syncthreads();

#pragma unroll
    for (int fm = 0; fm < 2; fm++) {
        int row0 = mw * 32 + fm * 16 + g;
        float inv0 = 1.f / dens[row0];
        float inv1 = 1.f / dens[row0 + 8];
        float* o0 = out + ((size_t)(b * NN + i0 + row0)) * FOUT;
        float* o1 = out + ((size_t)(b * NN + i0 + row0 + 8)) * FOUT;
#pragma unroll
        for (int fn = 0; fn < 8; fn++) {
            int col = nw * 64 + fn * 8 + t * 2;
            float x0 = acc[fm][fn][0] * inv0;
            float x1 = acc[fm][fn][1] * inv0;
            float x2 = acc[fm][fn][2] * inv1;
            float x3 = acc[fm][fn][3] * inv1;
            float2 v0, v1;
            v0.x = x0 > 0.f ? x0 : expm1f(x0);
            v0.y = x1 > 0.f ? x1 : expm1f(x1);
            v1.x = x2 > 0.f ? x2 : expm1f(x2);
            v1.y = x3 > 0.f ? x3 : expm1f(x3);
            *(float2*)&o0[col] = v0;
            *(float2*)&o1[col] = v1;
        }
    }
}

// ---------------------------------------------------------------------------
extern "C" void kernel_launch(void* const* d_in, const int* in_sizes, int n_in,
                              void* d_out, int out_size) {
    const float* h   = (const float*)d_in[0];
    const int*   adj = (const int*)d_in[1];
    const float* W   = (const float*)d_in[2];
    const float* a   = (const float*)d_in[3];
    float*       out = (float*)d_out;

    cudaFuncSetAttribute(wh_tc, cudaFuncAttributeMaxDynamicSharedMemorySize,
                         WH_SMEM_F * 4);
    cudaFuncSetAttribute(attn_mma, cudaFuncAttributeMaxDynamicSharedMemorySize,
                         ATTN_SMEM_F * 4);

    wt_kernel<<<dim3(FIN / 32, FOUT / 32), 256>>>(W);
    wh_tc<<<(BB * NN) / 64, 256, WH_SMEM_F * 4>>>(h, a);
    attn_mma<<<dim3(NN / 128, BB), 512, ATTN_SMEM_F * 4>>>(adj, out);
}

// round 16
// speedup vs baseline: 1.7316x; 1.0042x over previous
#include <cuda_runtime.h>
#include <cuda_fp16.h>
#include <math.h>
#include <stdint.h>

#define BB 8
#define NN 2048
#define FIN 512
#define FOUT 256
#define ALPHA 0.2f

// Scratch (allocation-free rule: __device__ globals)
__device__ __half   g_WT[FOUT * FIN];       // [n][k] fp16 (wh B operand)
__device__ __half   g_WhT[BB * FOUT * NN];  // [b][n][j] fp16 (attn B operand)
__device__ float    g_f1[BB * NN];
__device__ float    g_f2[BB * NN];
__device__ float2   g_e1[BB * NN];          // {exp(f1), exp(ALPHA*f1)}
__device__ float2   g_e2[BB * NN];          // {exp(f2), exp(ALPHA*f2)}
__device__ unsigned g_m2bits[BB * 2];       // per-batch max e2p/e2n bits (idempotent)

// ---------------------------------------------------------------------------
// mma.sync + cp.async helpers (sm_80 baseline — PTX target-safe)
// ---------------------------------------------------------------------------
__device__ __forceinline__ void mma_f16(float d[4], const uint32_t a[4],
                                        uint32_t b0, uint32_t b1) {
    asm volatile(
        "mma.sync.aligned.m16n8k16.row.col.f32.f16.f16.f32 "
        "{%0,%1,%2,%3}, {%4,%5,%6,%7}, {%8,%9}, {%0,%1,%2,%3};"
        : "+f"(d[0]), "+f"(d[1]), "+f"(d[2]), "+f"(d[3])
        : "r"(a[0]), "r"(a[1]), "r"(a[2]), "r"(a[3]), "r"(b0), "r"(b1));
}
__device__ __forceinline__ void cp_async16(uint32_t dst_smem, const void* src) {
    asm volatile("cp.async.cg.shared.global [%0], [%1], 16;"
                 :: "r"(dst_smem), "l"(src));
}
#define CP_COMMIT() asm volatile("cp.async.commit_group;" ::: "memory")
#define CP_WAIT(n)  asm volatile("cp.async.wait_group %0;" :: "n"(n) : "memory")
__device__ __forceinline__ uint32_t h2bits(float x, float y) {
    __half2 h = __floats2half2_rn(x, y);
    return *(uint32_t*)&h;
}

// ---------------------------------------------------------------------------
// Kernel 0: W [k][n] fp32 -> g_WT [n][k] fp16 (tiled transpose, tiny)
// ---------------------------------------------------------------------------
__global__ __launch_bounds__(256) void wt_kernel(const float* __restrict__ W) {
    __shared__ float tile[32][33];
    const int k0 = blockIdx.x * 32;
    const int n0 = blockIdx.y * 32;
    const int tx = threadIdx.x & 31, ty = threadIdx.x >> 5;
#pragma unroll
    for (int i = 0; i < 32; i += 8)
        tile[ty + i][tx] = W[(size_t)(k0 + ty + i) * FOUT + n0 + tx];
    __syncthreads();
#pragma unroll
    for (int i = 0; i < 32; i += 8)
        g_WT[(size_t)(n0 + ty + i) * FIN + k0 + tx] = __float2half_rn(tile[tx][ty + i]);
}

// ---------------------------------------------------------------------------
// Kernel 1: Wh = h @ W, fp16 m16n8k16 (fp32 acc), fused f1/f2/exp epilogue.
// (R11 version — unchanged)
// ---------------------------------------------------------------------------
#define WH_AS  0
#define WH_BS  1280
#define WH_SA  6400
#define WH_F1P 6912
#define WH_F2P 7168
#define WH_SMEM_F 7424

__global__ __launch_bounds__(256, 2) void wh_tc(const float* __restrict__ h,
                                                const float* __restrict__ aa) {
    extern __shared__ float sm[];
    float* A_s  = sm + WH_AS;
    float* B_s  = sm + WH_BS;
    float* sA   = sm + WH_SA;
    float* f1p  = sm + WH_F1P;
    float* f2p  = sm + WH_F2P;

    const int tid  = threadIdx.x;
    const int warp = tid >> 5;
    const int lane = tid & 31;
    const int mw   = warp >> 2;
    const int nw   = warp & 3;
    const int g    = lane >> 2;
    const int t    = lane & 3;
    const int row0 = blockIdx.x * 64;

    sA[tid]       = aa[tid];
    sA[tid + 256] = aa[tid + 256];

    float acc[2][8][4];
#pragma unroll
    for (int fm = 0; fm < 2; fm++)
#pragma unroll
        for (int fn = 0; fn < 8; fn++)
#pragma unroll
            for (int c = 0; c < 4; c++) acc[fm][fn][c] = 0.f;

    const int r  = tid >> 2, q = tid & 3;
    const int bn = tid >> 2;
    const int bc = tid & 3;
    const uint32_t smem_base = (uint32_t)__cvta_generic_to_shared(sm);

    for (int k0 = 0; k0 < FIN; k0 += 32) {
        {
            const float* src = h + (size_t)(row0 + r) * FIN + k0 + q * 8;
            float4 v0 = *(const float4*)src;
            float4 v1 = *(const float4*)(src + 4);
            float* ad = A_s + r * 20 + q * 4;
            ad[0] = __uint_as_float(h2bits(v0.x, v0.y));
            ad[1] = __uint_as_float(h2bits(v0.z, v0.w));
            ad[2] = __uint_as_float(h2bits(v1.x, v1.y));
            ad[3] = __uint_as_float(h2bits(v1.z, v1.w));
        }
#pragma unroll
        for (int p = 0; p < 4; p++) {
            int n = bn + 64 * p;
            const __half* src = g_WT + (size_t)n * FIN + k0 + bc * 8;
            uint32_t dst = smem_base + (WH_BS + n * 20 + bc * 4) * 4;
            cp_async16(dst, src);
        }
        CP_COMMIT();
        CP_WAIT(0);
        __syncthreads();

#pragma unroll
        for (int fk = 0; fk < 2; fk++) {
            uint32_t A[2][4];
#pragma unroll
            for (int fm = 0; fm < 2; fm++) {
                const float* wa = A_s + (mw * 32 + fm * 16 + g) * 20 + fk * 8 + t;
                A[fm][0] = __float_as_uint(wa[0]);
                A[fm][1] = __float_as_uint(wa[160]);
                A[fm][2] = __float_as_uint(wa[4]);
                A[fm][3] = __float_as_uint(wa[164]);
            }
#pragma unroll
            for (int fn = 0; fn < 8; fn++) {
                const float* wb = B_s + (nw * 64 + fn * 8 + g) * 20 + fk * 8 + t;
                uint32_t b0 = __float_as_uint(wb[0]);
                uint32_t b1 = __float_as_uint(wb[4]);
                mma_f16(acc[0][fn], A[0], b0, b1);
                mma_f16(acc[1][fn], A[1], b0, b1);
            }
        }
        __syncthreads();
    }

#pragma unroll
    for (int fm = 0; fm < 2; fm++) {
        int rr = row0 + mw * 32 + fm * 16 + g;
        int bb = rr >> 11;
        int jj = rr & (NN - 1);
#pragma unroll
        for (int fn = 0; fn < 8; fn++) {
            int col = nw * 64 + fn * 8 + t * 2;
            size_t base = ((size_t)bb * FOUT + col) * NN + jj;
            g_WhT[base]          = __float2half_rn(acc[fm][fn][0]);
            g_WhT[base + NN]     = __float2half_rn(acc[fm][fn][1]);
            g_WhT[base + 8]      = __float2half_rn(acc[fm][fn][2]);
            g_WhT[base + NN + 8] = __float2half_rn(acc[fm][fn][3]);
        }
    }

    {
        float p1[4] = {0.f, 0.f, 0.f, 0.f};
        float p2[4] = {0.f, 0.f, 0.f, 0.f};
#pragma unroll
        for (int fm = 0; fm < 2; fm++)
#pragma unroll
            for (int fn = 0; fn < 8; fn++) {
                int col = nw * 64 + fn * 8 + t * 2;
                float a10 = sA[col], a11 = sA[col + 1];
                float a20 = sA[256 + col], a21 = sA[256 + col + 1];
                p1[fm * 2 + 0] += acc[fm][fn][0] * a10 + acc[fm][fn][1] * a11;
                p1[fm * 2 + 1] += acc[fm][fn][2] * a10 + acc[fm][fn][3] * a11;
                p2[fm * 2 + 0] += acc[fm][fn][0] * a20 + acc[fm][fn][1] * a21;
                p2[fm * 2 + 1] += acc[fm][fn][2] * a20 + acc[fm][fn][3] * a21;
            }
#pragma unroll
        for (int off = 1; off <= 2; off <<= 1)
#pragma unroll
            for (int i = 0; i < 4; i++) {
                p1[i] += __shfl_xor_sync(0xFFFFFFFFu, p1[i], off);
                p2[i] += __shfl_xor_sync(0xFFFFFFFFu, p2[i], off);
            }
        if (t == 0) {
#pragma unroll
            for (int fm = 0; fm < 2; fm++)
#pragma unroll
                for (int hi = 0; hi < 2; hi++) {
                    int rowl = mw * 32 + fm * 16 + g + hi * 8;
                    f1p[rowl * 4 + nw] = p1[fm * 2 + hi];
                    f2p[rowl * 4 + nw] = p2[fm * 2 + hi];
                }
        }
    }
    __syncthreads();
    if (tid < 64) {
        float s1 = ((f1p[tid * 4] + f1p[tid * 4 + 1]) + f1p[tid * 4 + 2]) + f1p[tid * 4 + 3];
        float s2 = ((f2p[tid * 4] + f2p[tid * 4 + 1]) + f2p[tid * 4 + 2]) + f2p[tid * 4 + 3];
        int rr = row0 + tid;
        int bb = rr >> 11;
        g_f1[rr] = s1;
        g_f2[rr] = s2;
        float e2p = __expf(s2), e2n = __expf(ALPHA * s2);
        g_e1[rr] = make_float2(__expf(s1), __expf(ALPHA * s1));
        g_e2[rr] = make_float2(e2p, e2n);
        atomicMax(&g_m2bits[bb * 2 + 0], __float_as_uint(e2p));
        atomicMax(&g_m2bits[bb * 2 + 1], __float_as_uint(e2n));
    }
}

// ---------------------------------------------------------------------------
// Kernel 2: fused masked-softmax aggregation, fp16 m16n8k16 (fp32 acc).
// SINGLE-BARRIER software pipeline: per iter, issue MMAs(tt) first, then
// fill w(tt+1) + cp.async WhT(tt+2) (4-buffer rotation, depth 2), one
// CP_WAIT(1) + one __syncthreads. Fill hides in HMMA backpressure gaps.
// Arithmetic identical to R11.
// ---------------------------------------------------------------------------
#define SM_WH   0                      // 4 bufs x 5120 = 20480 floats
#define SM_W    20480                  // 2 bufs x 2560 = 5120
#define SM_F2   25600                  // 2048
#define SM_E2   27648                  // 4096
#define SM_F1   31744                  // 128
#define SM_DEN  31872                  // 128
#define ATTN_SMEM_F 32000              // 128000 B

__global__ __launch_bounds__(512, 1) void attn_mma(const int* __restrict__ adj,
                                                   float* __restrict__ out) {
    extern __shared__ float smem[];
    float*  f2s  = smem + SM_F2;
    float2* e2s  = (float2*)(smem + SM_E2);
    float*  f1s  = smem + SM_F1;
    float*  dens = smem + SM_DEN;

    const int tid  = threadIdx.x;
    const int warp = tid >> 5;
    const int lane = tid & 31;
    const int mw   = warp >> 2;
    const int nw   = warp & 3;
    const int g    = lane >> 2;
    const int t    = lane & 3;
    const int b    = blockIdx.y;
    const int i0   = blockIdx.x * 128;

    {
        const float4* f2g = (const float4*)(g_f2 + b * NN);
        ((float4*)f2s)[tid] = f2g[tid];
        const float4* e2g = (const float4*)(g_e2 + b * NN);
        ((float4*)e2s)[tid]       = e2g[tid];
        ((float4*)e2s)[tid + 512] = e2g[tid + 512];
        if (tid < 128) f1s[tid] = g_f1[b * NN + i0 + tid];
    }

    const int    r    = tid >> 2;
    const int    jq   = tid & 3;
    const int4*  arow = (const int4*)(adj + ((size_t)(b * NN + i0 + r)) * NN + jq * 8);
    const float2 e1   = g_e1[b * NN + i0 + r];
    const __half* whTsrc = g_WhT + (size_t)b * FOUT * NN;

    const float M2p  = __uint_as_float(g_m2bits[b * 2 + 0]);
    const float M2n  = __uint_as_float(g_m2bits[b * 2 + 1]);
    const float sinv = 1.f / fmaxf(e1.x * M2p, e1.y * M2n);
    const float c1p  = e1.x * sinv;
    const float c1n  = e1.y * sinv;

    const int cpn = tid >> 2;
    const int cpc = tid & 3;
    const uint32_t smem_base = (uint32_t)__cvta_generic_to_shared(smem);

    float acc[2][8][4];
#pragma unroll
    for (int fm = 0; fm < 2; fm++)
#pragma unroll
        for (int fn = 0; fn < 8; fn++)
#pragma unroll
            for (int c = 0; c < 4; c++) acc[fm][fn][c] = 0.f;

    // prologue: cp.async WhT tiles 0,1 into bufs 0,1 (two groups)
#pragma unroll
    for (int tpre = 0; tpre < 2; tpre++) {
#pragma unroll
        for (int p = 0; p < 2; p++) {
            int n = cpn + 128 * p;
            const __half* src = whTsrc + (size_t)n * NN + tpre * 32 + cpc * 8;
            uint32_t dst = smem_base + (SM_WH + tpre * 5120 + n * 20 + cpc * 4) * 4;
            cp_async16(dst, src);
        }
        CP_COMMIT();
    }

    __syncthreads();              // tables staged
    const float f1v = f1s[r];
    float den = 0.f;

    // helper values for w fill
    // prologue: fill w(0) into wbuf0 (direct adj load), prefetch adj(1)
    int4 avA, avB;
    {
        int4 a0 = arow[0], b0v = arow[1];
        int am[8] = {a0.x, a0.y, a0.z, a0.w, b0v.x, b0v.y, b0v.z, b0v.w};
        const float*  f2p = f2s + jq * 8;
        const float2* e2p = e2s + jq * 8;
        float wv[8];
#pragma unroll
        for (int u = 0; u < 8; u++) {
            float  e  = f1v + f2p[u];
            float2 e2 = e2p[u];
            float  w  = (e > 0.f) ? c1p * e2.x : c1n * e2.y;
            wv[u] = (am[u] > 0) ? w : 0.f;
        }
        uint32_t pk[4];
#pragma unroll
        for (int i = 0; i < 4; i++) {
            __half2 hp = __floats2half2_rn(wv[2 * i], wv[2 * i + 1]);
            pk[i] = *(uint32_t*)&hp;
            float2 hf = __half22float2(hp);
            den += hf.x + hf.y;
        }
        float* wd = smem + SM_W + r * 20 + jq * 4;
        *(float4*)wd = make_float4(__uint_as_float(pk[0]), __uint_as_float(pk[1]),
                                   __uint_as_float(pk[2]), __uint_as_float(pk[3]));
        avA = arow[8];
        avB = arow[9];
    }
    CP_WAIT(1);                   // tile 0 arrived
    __syncthreads();              // w(0) + WhT(0) visible

    for (int tt = 0; tt < 64; tt++) {
        const float* w_s = smem + SM_W + (tt & 1) * 2560;
        const float* B_s = smem + SM_WH + (tt & 3) * 5120;

        // ---- MMA phase for tile tt (issued first; pipe churns below) ----
#pragma unroll
        for (int fk = 0; fk < 2; fk++) {
            uint32_t A[2][4];
#pragma unroll
            for (int fm = 0; fm < 2; fm++) {
                const float* wa = w_s + (mw * 32 + fm * 16 + g) * 20 + fk * 8 + t;
                A[fm][0] = __float_as_uint(wa[0]);
                A[fm][1] = __float_as_uint(wa[160]);
                A[fm][2] = __float_as_uint(wa[4]);
                A[fm][3] = __float_as_uint(wa[164]);
            }
#pragma unroll
            for (int fn = 0; fn < 8; fn++) {
                const float* wb = B_s + (nw * 64 + fn * 8 + g) * 20 + fk * 8 + t;
                uint32_t b0 = __float_as_uint(wb[0]);
                uint32_t b1 = __float_as_uint(wb[4]);
                mma_f16(acc[0][fn], A[0], b0, b1);
                mma_f16(acc[1][fn], A[1], b0, b1);
            }
        }

        // ---- fill w(tt+1) into other w-buffer (issues under MMA churn) ----
        if (tt < 63) {
            const int jn = (tt + 1) * 32;
            int am[8] = {avA.x, avA.y, avA.z, avA.w, avB.x, avB.y, avB.z, avB.w};
            const float*  f2p = f2s + jn + jq * 8;
            const float2* e2p = e2s + jn + jq * 8;
            float wv[8];
#pragma unroll
            for (int u = 0; u < 8; u++) {
                float  e  = f1v + f2p[u];
                float2 e2 = e2p[u];
                float  w  = (e > 0.f) ? c1p * e2.x : c1n * e2.y;
                wv[u] = (am[u] > 0) ? w : 0.f;
            }
            uint32_t pk[4];
#pragma unroll
            for (int i = 0; i < 4; i++) {
                __half2 hp = __floats2half2_rn(wv[2 * i], wv[2 * i + 1]);
                pk[i] = *(uint32_t*)&hp;
                float2 hf = __half22float2(hp);
                den += hf.x + hf.y;
            }
            float* wd = smem + SM_W + ((tt + 1) & 1) * 2560 + r * 20 + jq * 4;
            *(float4*)wd = make_float4(__uint_as_float(pk[0]), __uint_as_float(pk[1]),
                                       __uint_as_float(pk[2]), __uint_as_float(pk[3]));
            if (tt < 62) {
                avA = arow[(tt + 2) * 8];
                avB = arow[(tt + 2) * 8 + 1];
            }
        }
        // ---- cp.async WhT(tt+2) into buf (tt+2)&3 ----
        if (tt < 62) {
#pragma unroll
            for (int p = 0; p < 2; p++) {
                int n = cpn + 128 * p;
                const __half* src = whTsrc + (size_t)n * NN + (tt + 2) * 32 + cpc * 8;
                uint32_t dst = smem_base +
                    (SM_WH + ((tt + 2) & 3) * 5120 + n * 20 + cpc * 4) * 4;
                cp_async16(dst, src);
            }
        }
        CP_COMMIT();              // unconditional: keeps group count uniform
        CP_WAIT(1);               // tile tt+1 arrived (FIFO group order)
        __syncthreads();
    }

    den += __shfl_xor_sync(0xFFFFFFFFu, den, 1);
    den += __shfl_xor_sync(0xFFFFFFFFu, den, 2);
    if (jq == 0) dens[r] = den;
    __syncthreads();

#pragma unroll
    for (int fm = 0; fm < 2; fm++) {
        int row0 = mw * 32 + fm * 16 + g;
        float inv0 = 1.f / dens[row0];
        float inv1 = 1.f / dens[row0 + 8];
        float* o0 = out + ((size_t)(b * NN + i0 + row0)) * FOUT;
        float* o1 = out + ((size_t)(b * NN + i0 + row0 + 8)) * FOUT;
#pragma unroll
        for (int fn = 0; fn < 8; fn++) {
            int col = nw * 64 + fn * 8 + t * 2;
            float x0 = acc[fm][fn][0] * inv0;
            float x1 = acc[fm][fn][1] * inv0;
            float x2 = acc[fm][fn][2] * inv1;
            float x3 = acc[fm][fn][3] * inv1;
            float2 v0, v1;
            v0.x = x0 > 0.f ? x0 : expm1f(x0);
            v0.y = x1 > 0.f ? x1 : expm1f(x1);
            v1.x = x2 > 0.f ? x2 : expm1f(x2);
            v1.y = x3 > 0.f ? x3 : expm1f(x3);
            *(float2*)&o0[col] = v0;
            *(float2*)&o1[col] = v1;
        }
    }
}

// ---------------------------------------------------------------------------
extern "C" void kernel_launch(void* const* d_in, const int* in_sizes, int n_in,
                              void* d_out, int out_size) {
    const float* h   = (const float*)d_in[0];
    const int*   adj = (const int*)d_in[1];
    const float* W   = (const float*)d_in[2];
    const float* a   = (const float*)d_in[3];
    float*       out = (float*)d_out;

    cudaFuncSetAttribute(wh_tc, cudaFuncAttributeMaxDynamicSharedMemorySize,
                         WH_SMEM_F * 4);
    cudaFuncSetAttribute(attn_mma, cudaFuncAttributeMaxDynamicSharedMemorySize,
                         ATTN_SMEM_F * 4);

    wt_kernel<<<dim3(FIN / 32, FOUT / 32), 256>>>(W);
    wh_tc<<<(BB * NN) / 64, 256, WH_SMEM_F * 4>>>(h, a);
    attn_mma<<<dim3(NN / 128, BB), 512, ATTN_SMEM_F * 4>>>(adj, out);
}